// round 6
// baseline (speedup 1.0000x reference)
#include <cuda_runtime.h>

// ConditionalSplineSQ2D: out[b] = sum_{g,h,c} param[b,g,h,ii]*param[b,g,h,jj]*coef[g,h,c]
// B=4096, G*G=961 cells, P=8, C=36. Pure HBM stream: 126MB read once.
//
// Thread t owns cell t. Coefs live in SMEM transposed+padded to 1024 cells
// (cfs[c*1024 + cell], conflict-free LDS, zero for pad cells) -- frees the
// regfile (R1/R4 burned 36 regs/thread on coefs, pinning 64 regs and capping
// per-thread MLP). Each iteration processes TWO b's with plain scalar FMA:
// one LDS per coef feeds both b's, and the next pair's 4x LDG.128 prefetch
// keeps 64B/thread (64KB/SM) of DRAM reads in flight. Reduction batched:
// one __syncthreads per 4 pairs, warp w finalizes b_w.

#define GG     961
#define CW     1024            // padded cell count (power of 2)
#define CC     36
#define NTHR   1024
#define PAIRS  4               // pairs per reduction batch (8 b's)
#define SMEM_DYN (CC * CW * 4) // 147456 B

extern __shared__ float cfs[];  // [CC][CW] transposed coefs, pad cells = 0

__global__ __launch_bounds__(NTHR, 1)
void sq2d_kernel(const float* __restrict__ param,
                 const float* __restrict__ coef,
                 float* __restrict__ out,
                 int nB, int stride)
{
    __shared__ float red[2][PAIRS][2][32];

    const int tid  = threadIdx.x;
    const int lane = tid & 31;
    const int warp = tid >> 5;
    const int cell = (tid < GG) ? tid : (GG - 1);   // pad threads dup cell 960

    // Transposed fill: cfs[c][cell] = coef[cell][c]; zero for cell >= 961.
    for (int idx = tid; idx < CW * CC; idx += NTHR) {
        int cel = idx / CC;
        int c   = idx - cel * CC;
        cfs[c * CW + cel] = (idx < GG * CC) ? coef[idx] : 0.0f;
    }
    __syncthreads();

    const float4* pbase = reinterpret_cast<const float4*>(param) + (size_t)cell * 2;
    const size_t bstep4 = (size_t)GG * 2;
    const int pstride = 2 * stride;

    // Prefetch first pair (b, b+stride).
    float4 n00, n01, n10, n11;
    int b = blockIdx.x;
    if (b < nB)          { const float4* p = pbase + (size_t)b * bstep4;            n00 = p[0]; n01 = p[1]; }
    if (b + stride < nB) { const float4* p = pbase + (size_t)(b + stride) * bstep4; n10 = p[0]; n11 = p[1]; }

    int buf = 0;
    while (b < nB) {
        const int bstart = b;
        int npairs = 0;

#pragma unroll 1
        for (int k2 = 0; k2 < PAIRS && b < nB; k2++) {
            float4 a00 = n00, a01 = n01, a10 = n10, a11 = n11;

            // Prefetch the next pair immediately; it lands while this pair
            // computes and the batch-mates run.
            const int bn = b + pstride;
            if (bn < nB)          { const float4* p = pbase + (size_t)bn * bstep4;            n00 = p[0]; n01 = p[1]; }
            if (bn + stride < nB) { const float4* p = pbase + (size_t)(bn + stride) * bstep4; n10 = p[0]; n11 = p[1]; }

            float p0[8] = { a00.x, a00.y, a00.z, a00.w, a01.x, a01.y, a01.z, a01.w };
            float p1[8] = { a10.x, a10.y, a10.z, a10.w, a11.x, a11.y, a11.z, a11.w };

            // acc = sum_{i<=j} cf[c(i,j)] * p_i * p_j for both b's.
            // 36 LDS.32 (shared by the pair) + 88 scalar FMA.
            float acc0 = 0.0f, acc1 = 0.0f;
            int c = 0;
#pragma unroll
            for (int i = 0; i < 8; i++) {
                float q0 = 0.0f, q1 = 0.0f;
#pragma unroll
                for (int j = i; j < 8; j++) {
                    float cf = cfs[c * CW + tid];   // imm offset, conflict-free
                    q0 = fmaf(cf, p0[j], q0);
                    q1 = fmaf(cf, p1[j], q1);
                    c++;
                }
                acc0 = fmaf(p0[i], q0, acc0);
                acc1 = fmaf(p1[i], q1, acc1);
            }

            // Warp reduce both halves; no block barrier here.
#pragma unroll
            for (int o = 16; o > 0; o >>= 1) {
                acc0 += __shfl_xor_sync(0xffffffffu, acc0, o);
                acc1 += __shfl_xor_sync(0xffffffffu, acc1, o);
            }
            if (lane == 0) {
                red[buf][k2][0][warp] = acc0;
                red[buf][k2][1][warp] = acc1;
            }

            b = bn;
            npairs++;
        }

        __syncthreads();   // one barrier per batch (up to 8 b's)

        // Warp w finalizes b = bstart + w*stride  (w = 2*pair + half).
        if (warp < 2 * npairs) {
            float v = red[buf][warp >> 1][warp & 1][lane];
#pragma unroll
            for (int o = 16; o > 0; o >>= 1)
                v += __shfl_xor_sync(0xffffffffu, v, o);
            const int bo = bstart + warp * stride;
            if (lane == 0 && bo < nB) out[bo] = v;
        }

        buf ^= 1;
    }
}

extern "C" void kernel_launch(void* const* d_in, const int* in_sizes, int n_in,
                              void* d_out, int out_size)
{
    const float* param = (const float*)d_in[0];   // [B, 31, 31, 8] f32
    const float* coef  = (const float*)d_in[1];   // [31, 31, 36]   f32
    float* out = (float*)d_out;                    // [B] f32

    const int nB = in_sizes[0] / (GG * 8);

    static int configured = -1;
    if (configured < 0) {
        cudaFuncSetAttribute(sq2d_kernel,
                             cudaFuncAttributeMaxDynamicSharedMemorySize, SMEM_DYN);
        configured = 1;
    }

    int dev = 0, sms = 0;
    cudaGetDevice(&dev);
    cudaDeviceGetAttribute(&sms, cudaDevAttrMultiProcessorCount, dev);
    if (sms <= 0) sms = 148;
    if (sms > nB) sms = nB;

    sq2d_kernel<<<sms, NTHR, SMEM_DYN>>>(param, coef, out, nB, sms);
}

// round 7
// speedup vs baseline: 1.3651x; 1.3651x over previous
#include <cuda_runtime.h>

// ConditionalSplineSQ2D: out[b] = sum_{g,h,c} param[b,g,h,ii]*param[b,g,h,jj]*coef[g,h,c]
// B=4096, G*G=961 cells, P=8, C=36. Pure HBM stream: 126MB read once.
//
// R1 core (thread t owns cell t, 36 coefs in registers, 2x LDG.128 per b,
// 1-deep register prefetch, 44 FMA) with the ENTIRE block reduction replaced
// by one atomicAdd per warp per b (lane 0, after a 5-shfl warp reduce).
// No smem, no __syncthreads in the loop: warps are fully decoupled, so the
// per-SMSP round-robin across 8 independent warps hides DRAM latency that
// R1's coupled epilogue (shfl chain + barrier + second reduce) exposed.
// out[] is zeroed by a prologue kernel (atomics accumulate into it).

#define GG    961
#define CC    36
#define NTHR  1024

__global__ void zero_kernel(float* __restrict__ out, int n)
{
    int i = blockIdx.x * blockDim.x + threadIdx.x;
    if (i < n) out[i] = 0.0f;
}

__global__ __launch_bounds__(NTHR, 1)
void sq2d_kernel(const float* __restrict__ param,
                 const float* __restrict__ coef,
                 float* __restrict__ out,
                 int nB, int stride)
{
    const int tid  = threadIdx.x;
    const int lane = tid & 31;
    const bool active = (tid < GG);
    const int cell = active ? tid : (GG - 1);   // pad threads dup cell 960

    // 36 coefficients in registers for the whole kernel (0 for pad threads).
    float cf[CC];
#pragma unroll
    for (int c = 0; c < CC; c++)
        cf[c] = active ? coef[cell * CC + c] : 0.0f;

    const float4* pbase = reinterpret_cast<const float4*>(param) + (size_t)cell * 2;
    const size_t bstep4 = (size_t)GG * 2;

    int b = blockIdx.x;
    float4 n0, n1;
    if (b < nB) {
        const float4* p = pbase + (size_t)b * bstep4;
        n0 = p[0];
        n1 = p[1];
    }

#pragma unroll 1
    while (b < nB) {
        float4 a0 = n0, a1 = n1;

        // Prefetch next b right away; lands while we compute + reduce.
        const int bn = b + stride;
        if (bn < nB) {
            const float4* p = pbase + (size_t)bn * bstep4;
            n0 = p[0];
            n1 = p[1];
        }

        float pv[8] = { a0.x, a0.y, a0.z, a0.w, a1.x, a1.y, a1.z, a1.w };

        // acc = sum_{i<=j} cf[c(i,j)] * p_i * p_j : 44 FMA.
        float acc = 0.0f;
        int c = 0;
#pragma unroll
        for (int i = 0; i < 8; i++) {
            float q = 0.0f;
#pragma unroll
            for (int j = i; j < 8; j++)
                q = fmaf(cf[c++], pv[j], q);
            acc = fmaf(pv[i], q, acc);
        }

        // Warp reduce, then one red.global.add per warp. No block coupling.
#pragma unroll
        for (int o = 16; o > 0; o >>= 1)
            acc += __shfl_xor_sync(0xffffffffu, acc, o);
        if (lane == 0)
            atomicAdd(&out[b], acc);

        b = bn;
    }
}

extern "C" void kernel_launch(void* const* d_in, const int* in_sizes, int n_in,
                              void* d_out, int out_size)
{
    const float* param = (const float*)d_in[0];   // [B, 31, 31, 8] f32
    const float* coef  = (const float*)d_in[1];   // [31, 31, 36]   f32
    float* out = (float*)d_out;                    // [B] f32

    const int nB = in_sizes[0] / (GG * 8);

    int dev = 0, sms = 0;
    cudaGetDevice(&dev);
    cudaDeviceGetAttribute(&sms, cudaDevAttrMultiProcessorCount, dev);
    if (sms <= 0) sms = 148;
    if (sms > nB) sms = nB;

    zero_kernel<<<(out_size + NTHR - 1) / NTHR, NTHR>>>(out, out_size);
    sq2d_kernel<<<sms, NTHR>>>(param, coef, out, nB, sms);
}

// round 8
// speedup vs baseline: 1.5438x; 1.1309x over previous
#include <cuda_runtime.h>
#include <cstdint>

// ConditionalSplineSQ2D: out[b] = sum_{g,h,c} param[b,g,h,ii]*param[b,g,h,jj]*coef[g,h,c]
// B=4096, G*G=961 cells, P=8, C=36. Pure HBM stream: 126MB read once.
//
// Thread t owns cell t; 36 coefs in registers. The key fix vs R1/R4/R7:
// ptxas was eliminating the prefetch double-buffer copies, which (via WAR on
// the load destination regs) pushed the next-b LDGs to AFTER the FMA chain --
// loads were only in flight during the stall window (DRAM stuck ~50%).
// Here explicit volatile mov.f32 copies retire the old values in 4 cycles and
// the volatile ld.global.nc.v4 prefetch issues BEFORE the FMA chain, keeping
// every warp's 1KB outstanding through its whole iteration (~31KB/SM).
// Warps are staggered across the block's b-list (warp w starts at w*K/31,
// wrapping) so identical-cadence warps don't phase-lock into burst/drain.
// Per-b partials accumulate in a shared-memory slot via smem atomics (each b
// belongs to exactly one block); out[] is stored once at the end -- no zero
// kernel, no global atomics.

#define GG    961
#define CC    36
#define NTHR  992
#define NWARP 31

__global__ __launch_bounds__(NTHR, 1)
void sq2d_kernel(const float* __restrict__ param,
                 const float* __restrict__ coef,
                 float* __restrict__ out,
                 int nB, int stride)
{
    __shared__ float red[32];            // K <= ceil(4096/148) = 28

    const int tid  = threadIdx.x;
    const int lane = tid & 31;
    const int warp = tid >> 5;
    const bool active = (tid < GG);
    const int cell = active ? tid : (GG - 1);   // pad threads dup cell 960

    // 36 coefficients in registers (0 for pad threads).
    float cf[CC];
#pragma unroll
    for (int c = 0; c < CC; c++)
        cf[c] = active ? coef[cell * CC + c] : 0.0f;

    const int bid = blockIdx.x;
    const int K = (nB - bid + stride - 1) / stride;   // #b's for this block

    if (tid < 32) red[tid] = 0.0f;
    __syncthreads();

    const char* cellbase = (const char*)param + (size_t)cell * 32;
    const size_t bstep = (size_t)GG * 32;             // 30752 B per b

    // Stagger: warp w starts at index off_w in the block's b-list, wraps.
    int k = (warp * K) / NWARP;
    if (k >= K) k = K - 1;

    const char* ptr = cellbase + (size_t)(bid + k * stride) * bstep;

    float n0, n1, n2, n3, n4, n5, n6, n7;
    asm volatile("ld.global.nc.v4.f32 {%0,%1,%2,%3}, [%4];"
                 : "=f"(n0), "=f"(n1), "=f"(n2), "=f"(n3) : "l"(ptr));
    asm volatile("ld.global.nc.v4.f32 {%0,%1,%2,%3}, [%4+16];"
                 : "=f"(n4), "=f"(n5), "=f"(n6), "=f"(n7) : "l"(ptr));

#pragma unroll 1
    for (int j = 0; j < K; j++) {
        // Retire the loaded values into pv with explicit movs (kills the WAR
        // on n* in 4 cycles instead of at the end of the FMA chain).
        float pv0, pv1, pv2, pv3, pv4, pv5, pv6, pv7;
        asm volatile("mov.f32 %0, %1;" : "=f"(pv0) : "f"(n0));
        asm volatile("mov.f32 %0, %1;" : "=f"(pv1) : "f"(n1));
        asm volatile("mov.f32 %0, %1;" : "=f"(pv2) : "f"(n2));
        asm volatile("mov.f32 %0, %1;" : "=f"(pv3) : "f"(n3));
        asm volatile("mov.f32 %0, %1;" : "=f"(pv4) : "f"(n4));
        asm volatile("mov.f32 %0, %1;" : "=f"(pv5) : "f"(n5));
        asm volatile("mov.f32 %0, %1;" : "=f"(pv6) : "f"(n6));
        asm volatile("mov.f32 %0, %1;" : "=f"(pv7) : "f"(n7));

        const int kc = k;                 // b-slot this iteration reduces into

        // Advance (wrapping) and issue next prefetch NOW, before the FMAs.
        k = k + 1;
        if (k == K) k = 0;
        ptr = cellbase + (size_t)(bid + k * stride) * bstep;
        asm volatile("ld.global.nc.v4.f32 {%0,%1,%2,%3}, [%4];"
                     : "=f"(n0), "=f"(n1), "=f"(n2), "=f"(n3) : "l"(ptr));
        asm volatile("ld.global.nc.v4.f32 {%0,%1,%2,%3}, [%4+16];"
                     : "=f"(n4), "=f"(n5), "=f"(n6), "=f"(n7) : "l"(ptr));

        float pv[8] = { pv0, pv1, pv2, pv3, pv4, pv5, pv6, pv7 };

        // acc = sum_{i<=j} cf[c(i,j)] * p_i * p_j : 44 FMA.
        float acc = 0.0f;
        int c = 0;
#pragma unroll
        for (int i = 0; i < 8; i++) {
            float q = 0.0f;
#pragma unroll
            for (int jj = i; jj < 8; jj++)
                q = fmaf(cf[c++], pv[jj], q);
            acc = fmaf(pv[i], q, acc);
        }

        // Warp reduce, then one smem atomic per warp per b.
#pragma unroll
        for (int o = 16; o > 0; o >>= 1)
            acc += __shfl_xor_sync(0xffffffffu, acc, o);
        if (lane == 0)
            atomicAdd(&red[kc], acc);
    }

    __syncthreads();
    if (tid < K)
        out[bid + tid * stride] = red[tid];
}

extern "C" void kernel_launch(void* const* d_in, const int* in_sizes, int n_in,
                              void* d_out, int out_size)
{
    const float* param = (const float*)d_in[0];   // [B, 31, 31, 8] f32
    const float* coef  = (const float*)d_in[1];   // [31, 31, 36]   f32
    float* out = (float*)d_out;                    // [B] f32

    const int nB = in_sizes[0] / (GG * 8);

    int dev = 0, sms = 0;
    cudaGetDevice(&dev);
    cudaDeviceGetAttribute(&sms, cudaDevAttrMultiProcessorCount, dev);
    if (sms <= 0) sms = 148;
    if (sms > nB) sms = nB;

    sq2d_kernel<<<sms, NTHR>>>(param, coef, out, nB, sms);
}

// round 9
// speedup vs baseline: 1.5618x; 1.0117x over previous
#include <cuda_runtime.h>
#include <cstdint>

// ConditionalSplineSQ2D: out[b] = sum_{g,h,c} param[b,g,h,ii]*param[b,g,h,jj]*coef[g,h,c]
// B=4096, G*G=961 cells, P=8, C=36. Pure HBM stream: 126MB read once.
//
// DRAM% was pinned at ~50% across 5 designs because in-flight DRAM bytes/SM
// were register-limited (~31KB = the BW*latency knee; 36 coef regs/thread pin
// the kernel at the 64-reg cap so no deeper register buffering is possible).
// Fix: prefetch.global.L2 streams each warp's slab 6 iterations ahead --
// prefetches use no registers and no scoreboard, so DRAM depth is unbounded.
// Consumer LDGs then hit L2 (~250cyc), which 7.75 warps/SMSP hide without any
// double-buffer (mov machinery deleted; regs drop well under the cap).
// Warp w starts at k=w*K/31 (wrapping) so warps' DRAM demand is time-uniform;
// wrapped indices are that warp's own future b's, so wrapped prefetches are
// always useful. Per-b partials accumulate via smem atomics; single kernel.

#define GG    961
#define CC    36
#define NTHR  992
#define NWARP 31
#define PFD   6          // prefetch distance in b-iterations

__global__ __launch_bounds__(NTHR, 1)
void sq2d_kernel(const float* __restrict__ param,
                 const float* __restrict__ coef,
                 float* __restrict__ out,
                 int nB, int stride)
{
    __shared__ float red[32];            // K <= 28

    const int tid  = threadIdx.x;
    const int lane = tid & 31;
    const int warp = tid >> 5;
    const bool active = (tid < GG);
    const int cell = active ? tid : (GG - 1);   // pad threads dup cell 960

    // 36 coefficients in registers (0 for pad threads).
    float cf[CC];
#pragma unroll
    for (int c = 0; c < CC; c++)
        cf[c] = active ? coef[cell * CC + c] : 0.0f;

    const int bid = blockIdx.x;
    const int K = (nB - bid + stride - 1) / stride;   // b's for this block

    if (tid < 32) red[tid] = 0.0f;
    __syncthreads();

    const char* cellbase = (const char*)param + (size_t)cell * 32;
    const size_t bstep = (size_t)GG * 32 * (size_t)stride;   // bytes between this block's b's

    // Staggered start within the block's b-list.
    int k = (warp * K) / NWARP;
    if (k >= K) k = K - 1;
    int kp = k + PFD;
    while (kp >= K) kp -= K;

    const char* base0 = cellbase + (size_t)bid * (size_t)GG * 32;
    const char* ptr    = base0 + (size_t)k  * bstep;
    const char* pf_ptr = base0 + (size_t)kp * bstep;

    // Only 9 lanes/warp prefetch: lane%4==0 covers 128B-spaced lines across
    // the warp's 1KB slab; lane 31 covers the straddled tail line.
    const bool pf_lane = ((lane & 3) == 0) || (lane == 31);

#pragma unroll 1
    for (int j = 0; j < K; j++) {
        // Stream DRAM->L2 PFD iterations ahead (no regs, no scoreboard).
        if (pf_lane)
            asm volatile("prefetch.global.L2 [%0];" :: "l"(pf_ptr));
        kp++;
        pf_ptr += bstep;
        if (kp == K) { kp = 0; pf_ptr = base0; }

        // Consume this b (mostly L2 hits thanks to the prefetch stream).
        float pv[8];
        asm volatile("ld.global.nc.v4.f32 {%0,%1,%2,%3}, [%4];"
                     : "=f"(pv[0]), "=f"(pv[1]), "=f"(pv[2]), "=f"(pv[3]) : "l"(ptr));
        asm volatile("ld.global.nc.v4.f32 {%0,%1,%2,%3}, [%4+16];"
                     : "=f"(pv[4]), "=f"(pv[5]), "=f"(pv[6]), "=f"(pv[7]) : "l"(ptr));

        const int kc = k;
        k++;
        ptr += bstep;
        if (k == K) { k = 0; ptr = base0; }

        // acc = sum_{i<=j} cf[c(i,j)] * p_i * p_j : 44 FMA.
        float acc = 0.0f;
        int c = 0;
#pragma unroll
        for (int i = 0; i < 8; i++) {
            float q = 0.0f;
#pragma unroll
            for (int jj = i; jj < 8; jj++)
                q = fmaf(cf[c++], pv[jj], q);
            acc = fmaf(pv[i], q, acc);
        }

        // Warp reduce, then one smem atomic per warp per b.
#pragma unroll
        for (int o = 16; o > 0; o >>= 1)
            acc += __shfl_xor_sync(0xffffffffu, acc, o);
        if (lane == 0)
            atomicAdd(&red[kc], acc);
    }

    __syncthreads();
    if (tid < K)
        out[bid + tid * stride] = red[tid];
}

extern "C" void kernel_launch(void* const* d_in, const int* in_sizes, int n_in,
                              void* d_out, int out_size)
{
    const float* param = (const float*)d_in[0];   // [B, 31, 31, 8] f32
    const float* coef  = (const float*)d_in[1];   // [31, 31, 36]   f32
    float* out = (float*)d_out;                    // [B] f32

    const int nB = in_sizes[0] / (GG * 8);

    int dev = 0, sms = 0;
    cudaGetDevice(&dev);
    cudaDeviceGetAttribute(&sms, cudaDevAttrMultiProcessorCount, dev);
    if (sms <= 0) sms = 148;
    if (sms > nB) sms = nB;

    sq2d_kernel<<<sms, NTHR>>>(param, coef, out, nB, sms);
}

// round 10
// speedup vs baseline: 1.5756x; 1.0088x over previous
#include <cuda_runtime.h>
#include <cstdint>

// ConditionalSplineSQ2D: out[b] = sum_{g,h,c} param[b,g,h,ii]*param[b,g,h,jj]*coef[g,h,c]
// B=4096, G*G=961 cells, P=8, C=36. Pure HBM stream: 126MB read once.
//
// Latency-bound diagnosis (R9): nothing saturated, occupancy regfile-capped.
// This round removes warp-serial latency from the loop:
//  - prefetch.global.L1 two iterations ahead: consumer LDGs hit L1 (~39cyc)
//    instead of L2/DRAM; the prefetch stream (no regs, no scoreboard) carries
//    the DRAM latency.
//  - NO reduction in the loop: each thread STS's its per-b partial into
//    part[kc][tid] (written exactly once per (kc,tid)), no shfl chain, no
//    atomics, no barriers. After the loop, warp w sums slot w's 992 partials
//    (31 coalesced LDS + 5 shfl) and stores out[b_w]. Epilogue runs once.
// Warps stay staggered across the block's b-list so DRAM demand is uniform.

#define GG    961
#define CC    36
#define NTHR  992
#define NWARP 31
#define MAXK  32
#define PFD   2                      // L1 prefetch distance (iterations)
#define SMEM_DYN (MAXK * NTHR * 4)   // 126976 B partials

extern __shared__ float part[];      // [MAXK][NTHR]

__global__ __launch_bounds__(NTHR, 1)
void sq2d_kernel(const float* __restrict__ param,
                 const float* __restrict__ coef,
                 float* __restrict__ out,
                 int nB, int stride)
{
    const int tid  = threadIdx.x;
    const int lane = tid & 31;
    const int warp = tid >> 5;
    const bool active = (tid < GG);
    const int cell = active ? tid : (GG - 1);   // pad threads dup cell 960

    // 36 coefficients in registers (0 for pad threads -> their partials are 0).
    float cf[CC];
#pragma unroll
    for (int c = 0; c < CC; c++)
        cf[c] = active ? coef[cell * CC + c] : 0.0f;

    const int bid = blockIdx.x;
    const int K = (nB - bid + stride - 1) / stride;   // b's for this block (<=28)

    const char* base0 = (const char*)param + (size_t)cell * 32
                      + (size_t)bid * (size_t)GG * 32;
    const size_t bstep = (size_t)GG * 32 * (size_t)stride;

    // Staggered start within the block's b-list (uniform DRAM demand in time).
    int k = (warp * K) / NWARP;
    if (k >= K) k = K - 1;
    int kp = k + PFD;
    while (kp >= K) kp -= K;

    const char* ptr    = base0 + (size_t)k  * bstep;
    const char* pf_ptr = base0 + (size_t)kp * bstep;

    // 9 lanes/warp cover the warp's 1KB slab (8x 128B lines + straddle tail).
    const bool pf_lane = ((lane & 3) == 0) || (lane == 31);

#pragma unroll 1
    for (int j = 0; j < K; j++) {
        // Pull b+PFD all the way into L1 (no regs, no scoreboard).
        if (pf_lane)
            asm volatile("prefetch.global.L1 [%0];" :: "l"(pf_ptr));
        kp++;
        pf_ptr += bstep;
        if (kp == K) { kp = 0; pf_ptr = base0; }

        // Consume this b (L1 hits thanks to the prefetch stream).
        float pv[8];
        asm volatile("ld.global.nc.v4.f32 {%0,%1,%2,%3}, [%4];"
                     : "=f"(pv[0]), "=f"(pv[1]), "=f"(pv[2]), "=f"(pv[3]) : "l"(ptr));
        asm volatile("ld.global.nc.v4.f32 {%0,%1,%2,%3}, [%4+16];"
                     : "=f"(pv[4]), "=f"(pv[5]), "=f"(pv[6]), "=f"(pv[7]) : "l"(ptr));

        const int kc = k;
        k++;
        ptr += bstep;
        if (k == K) { k = 0; ptr = base0; }

        // acc = sum_{i<=j} cf[c(i,j)] * p_i * p_j : 44 FMA.
        float acc = 0.0f;
        int c = 0;
#pragma unroll
        for (int i = 0; i < 8; i++) {
            float q = 0.0f;
#pragma unroll
            for (int jj = i; jj < 8; jj++)
                q = fmaf(cf[c++], pv[jj], q);
            acc = fmaf(pv[i], q, acc);
        }

        // Raw partial to smem; no reduction, no sync, no atomics in the loop.
        part[kc * NTHR + tid] = acc;
    }

    __syncthreads();

    // Warp w reduces slot w: 992 partials = 31 coalesced LDS + warp shuffle.
    if (warp < K) {
        const float* row = &part[warp * NTHR];
        float v = 0.0f;
#pragma unroll
        for (int j = 0; j < NWARP; j++)
            v += row[j * 32 + lane];
#pragma unroll
        for (int o = 16; o > 0; o >>= 1)
            v += __shfl_xor_sync(0xffffffffu, v, o);
        if (lane == 0)
            out[bid + warp * stride] = v;
    }
}

extern "C" void kernel_launch(void* const* d_in, const int* in_sizes, int n_in,
                              void* d_out, int out_size)
{
    const float* param = (const float*)d_in[0];   // [B, 31, 31, 8] f32
    const float* coef  = (const float*)d_in[1];   // [31, 31, 36]   f32
    float* out = (float*)d_out;                    // [B] f32

    const int nB = in_sizes[0] / (GG * 8);

    static int configured = -1;
    if (configured < 0) {
        cudaFuncSetAttribute(sq2d_kernel,
                             cudaFuncAttributeMaxDynamicSharedMemorySize, SMEM_DYN);
        configured = 1;
    }

    int dev = 0, sms = 0;
    cudaGetDevice(&dev);
    cudaDeviceGetAttribute(&sms, cudaDevAttrMultiProcessorCount, dev);
    if (sms <= 0) sms = 148;

    int grid = sms;
    const int min_grid = (nB + MAXK - 1) / MAXK;   // keep K <= MAXK
    if (grid < min_grid) grid = min_grid;
    if (grid > nB) grid = nB;

    sq2d_kernel<<<grid, NTHR, SMEM_DYN>>>(param, coef, out, nB, grid);
}